// round 15
// baseline (speedup 1.0000x reference)
#include <cuda_runtime.h>

#define NB   512
#define NC   16
#define NT   2000
#define NRES 1024
#define NCLS 10
#define NBLK 148
#define NTHR 512
#define ALPHA 0.9f

// Persistent cross-CTA state.
__device__ float g_s[2][NB * NRES];            // spikes, [b][j] (classifier)
__device__ unsigned g_mask[2][NB][32];         // spike bitmask: bit i of word w = neuron 32w+i
__device__ float g_W2[8 * 32 * 32 * 128];      // Wres^T repacked: [j_tile][kc][k][j_local], 16KB blocks
__device__ float g_xT[(size_t)NT * NB * NC];   // x^T: [t][b][c]
__device__ unsigned g_bar_count;
__device__ unsigned g_bar_gen;

static __device__ __forceinline__ unsigned ld_acq(const unsigned* p) {
    unsigned v;
    asm volatile("ld.acquire.gpu.global.u32 %0, [%1];" : "=r"(v) : "l"(p) : "memory");
    return v;
}
static __device__ __forceinline__ void st_rel(unsigned* p, unsigned v) {
    asm volatile("st.release.gpu.global.u32 [%0], %1;" :: "l"(p), "r"(v) : "memory");
}

// Grid-wide barrier; all 148 CTAs resident (1 per SM).
static __device__ __forceinline__ void grid_barrier() {
    __syncthreads();
    if (threadIdx.x == 0) {
        unsigned gen = ld_acq(&g_bar_gen);
        __threadfence();
        if (atomicAdd(&g_bar_count, 1u) == NBLK - 1u) {
            g_bar_count = 0u;
            __threadfence();
            st_rel(&g_bar_gen, gen + 1u);
        } else {
            while (ld_acq(&g_bar_gen) == gen) { }
        }
    }
    __syncthreads();
}

static __device__ __forceinline__ unsigned long long pack2(float lo, float hi) {
    unsigned long long r;
    asm("mov.b64 %0, {%1, %2};" : "=l"(r) : "f"(lo), "f"(hi));
    return r;
}
static __device__ __forceinline__ void unpack2(unsigned long long p, float& lo, float& hi) {
    asm("mov.b64 {%0, %1}, %2;" : "=f"(lo), "=f"(hi) : "l"(p));
}
// add.rn.f32x2: two independent rn fp32 adds — per-lane bit-identical to __fadd_rn.
static __device__ __forceinline__ unsigned long long add2(unsigned long long a,
                                                          unsigned long long b) {
    unsigned long long r;
    asm("add.rn.f32x2 %0, %1, %2;" : "=l"(r) : "l"(a), "l"(b));
    return r;
}

// ---- bulk-async (TMA 1D) staging ----
static __device__ __forceinline__ void mbar_init(unsigned mbar, unsigned count) {
    asm volatile("mbarrier.init.shared.b64 [%0], %1;" :: "r"(mbar), "r"(count) : "memory");
}
static __device__ __forceinline__ void mbar_expect_tx(unsigned mbar, unsigned bytes) {
    asm volatile("mbarrier.arrive.expect_tx.shared.b64 _, [%0], %1;"
                 :: "r"(mbar), "r"(bytes) : "memory");
}
static __device__ __forceinline__ void mbar_wait(unsigned mbar, unsigned parity) {
    asm volatile(
        "{\n\t.reg .pred p;\n\t"
        "WAIT_%=:\n\t"
        "mbarrier.try_wait.parity.acquire.cta.shared::cta.b64 p, [%0], %1;\n\t"
        "@!p bra WAIT_%=;\n\t"
        "}" :: "r"(mbar), "r"(parity) : "memory");
}
static __device__ __forceinline__ void bulk_g2s(unsigned dst, const void* src,
                                                unsigned bytes, unsigned mbar) {
    asm volatile(
        "cp.async.bulk.shared::cluster.global.mbarrier::complete_tx::bytes "
        "[%0], [%1], %2, [%3];"
        :: "r"(dst), "l"(src), "r"(bytes), "r"(mbar) : "memory");
}

__global__ __launch_bounds__(NTHR, 1) void reservoir_persistent(
    const float* __restrict__ x,     // (NB, NC, NT)
    const float* __restrict__ Win,   // (NRES, NC)
    const float* __restrict__ Wres,  // (NRES, NRES)
    const float* __restrict__ Wclf,  // (NCLS, NRES)
    float* __restrict__ out)         // [NB*NCLS | NB*NRES]
{
    const int blk = blockIdx.x;
    const int tid = threadIdx.x;

    __shared__ __align__(128) float Bs[2][32][128];   // WresT chunk, dbl-buffered (TMA dst)
    __shared__ __align__(128) unsigned sMask[32][32]; // masks for this b-tile (TMA dst)
    __shared__ __align__(128) float sx[32][16];       // x_t tile, packed (TMA dst)
    __shared__ float sWin[128][17];
    __shared__ __align__(8) unsigned long long smbar[2];

    // ---- Phase 0 (all CTAs): one-time repack/transpose + mask zero ----
    {
        const int g0 = blk * NTHR + tid;
        const int gs = NBLK * NTHR;
        for (int i = g0; i < NRES * NRES; i += gs) {
            int j = i >> 10, k = i & (NRES - 1);
            g_W2[(((j >> 7) * 32 + (k >> 5)) << 12) + ((k & 31) << 7) + (j & 127)] = Wres[i];
        }
        for (size_t i = g0; i < (size_t)NT * NB * NC; i += (size_t)gs) {
            int t = (int)(i >> 13);
            int r = (int)(i & 8191);
            int b = r >> 4, c = r & 15;
            g_xT[i] = x[((size_t)(b * NC + c)) * NT + t];
        }
        for (int i = g0; i < NB * 32; i += gs)
            ((unsigned*)g_mask[0])[i] = 0u;
    }

    if (blk < 128) {
        // ------------- Reservoir path: CTA = 32 b x 128 j -------------------
        const int b0 = (blk >> 3) * 32;      // 16 b-tiles
        const int j0 = (blk & 7) * 128;      // 8 j-tiles
        const int jt = blk & 7;

        const int w    = tid >> 5;           // warp 0..15 -> rows w*2, w*2+1
        const int lane = tid & 31;           // lane -> cols lane*4 .. lane*4+3
        const int rl0 = w * 2;
        const int cl0 = lane * 4;

        const unsigned bs_u    = (unsigned)__cvta_generic_to_shared(Bs);
        const unsigned mask_u  = (unsigned)__cvta_generic_to_shared(sMask);
        const unsigned sx_u    = (unsigned)__cvta_generic_to_shared(sx);
        const unsigned mbar0_u = (unsigned)__cvta_generic_to_shared(&smbar[0]);
        const unsigned mbar1_u = (unsigned)__cvta_generic_to_shared(&smbar[1]);
        const unsigned bufBytes = 32 * 128 * 4;   // 16 KB

        if (tid == 0) {
            mbar_init(mbar0_u, 1);
            mbar_init(mbar1_u, 1);
        }

        // Zero step-0 float spikes.
        {
            float4 z = make_float4(0.f, 0.f, 0.f, 0.f);
#pragma unroll
            for (int i = 0; i < 2; i++)
                *(float4*)&g_s[0][(size_t)(b0 + rl0 + i) * NRES + j0 + cl0] = z;
        }
        for (int e = tid; e < 128 * 16; e += NTHR) {
            int r = e >> 4, c = e & 15;
            sWin[r][c] = Win[(size_t)(j0 + r) * NC + c];
        }

        float v[8], cnt[8];
#pragma unroll
        for (int q = 0; q < 8; q++) { v[q] = 0.f; cnt[q] = 0.f; }

        unsigned ph[2] = {0u, 0u};

        grid_barrier();   // also makes mbarrier init + g_W2 globally visible

        for (int t = 0; t < NT; ++t) {
            float* __restrict__ s_next = g_s[(t + 1) & 1];
            const int buf  = t & 1;
            const int nbuf = (t + 1) & 1;

            // Prologue: one thread bulk-stages chunk 31 + masks + x_t on mbar1.
            if (tid == 0) {
                mbar_expect_tx(mbar1_u, bufBytes + 4096u + 2048u);
                bulk_g2s(bs_u + bufBytes, &g_W2[(jt * 32 + 31) << 12], bufBytes, mbar1_u);
                bulk_g2s(mask_u, &g_mask[buf][b0][0], 4096u, mbar1_u);
                bulk_g2s(sx_u, &g_xT[(size_t)t * (NB * NC) + (size_t)b0 * NC], 2048u, mbar1_u);
            }

            // acc2[bb][h]: b row bb, j pair h (4 j per lane).
            unsigned long long acc2[2][2];
#pragma unroll
            for (int i = 0; i < 2; i++) {
                acc2[i][0] = pack2(0.f, 0.f);
                acc2[i][1] = pack2(0.f, 0.f);
            }

            for (int kc = 31; kc >= 0; --kc) {
                const int pb = kc & 1;
                // Prefetch chunk kc-1 into the other buffer (free since the
                // __syncthreads at the end of iteration kc+1).
                if (tid == 0 && kc > 0) {
                    const unsigned m = (kc & 1) ? mbar0_u : mbar1_u;  // (kc-1)&1
                    mbar_expect_tx(m, bufBytes);
                    bulk_g2s(bs_u + (unsigned)((kc - 1) & 1) * bufBytes,
                             &g_W2[(jt * 32 + (kc - 1)) << 12], bufBytes, m);
                }

                // Wait for chunk kc.
                mbar_wait(pb ? mbar1_u : mbar0_u, ph[pb]);
                // (phase flip recorded after the wait below)

                const unsigned bbase = bs_u + (unsigned)pb * bufBytes + (unsigned)cl0 * 4;
                // Sparse ordered accumulation, bit-exact (add.rn per active k,
                // skip inactive; k descending within chunk; chunks descending).
#pragma unroll
                for (int bb = 0; bb < 2; ++bb) {
                    unsigned m = sMask[rl0 + bb][kc];   // warp-uniform
                    unsigned long long a0 = acc2[bb][0];
                    unsigned long long a1 = acc2[bb][1];
                    while (m) {
                        int k = 31 - __clz(m);
                        m &= ~(1u << k);
                        unsigned long long w01, w23;
                        asm("ld.shared.v2.u64 {%0, %1}, [%2];"
                            : "=l"(w01), "=l"(w23)
                            : "r"(bbase + (unsigned)k * 512));
                        a0 = add2(a0, w01);
                        a1 = add2(a1, w23);
                    }
                    acc2[bb][0] = a0;
                    acc2[bb][1] = a1;
                }
                ph[pb] ^= 1u;
                __syncthreads();   // all readers done with buffer pb
            }

            // Epilogue (frozen): vn = rn(fma(0.9, v, d_in) + d_rec)
#pragma unroll
            for (int i = 0; i < 2; i++) {
                const int rb = rl0 + i;
                float d[4] = {0.f, 0.f, 0.f, 0.f};
#pragma unroll
                for (int c = 0; c < NC; c++) {
                    float xv = sx[rb][c];
#pragma unroll
                    for (int j = 0; j < 4; j++)
                        d[j] = __fmaf_rn(xv, sWin[cl0 + j][c], d[j]);
                }
                float r01[2], r23[2];
                unpack2(acc2[i][0], r01[0], r01[1]);
                unpack2(acc2[i][1], r23[0], r23[1]);
                float rr[4] = {r01[0], r01[1], r23[0], r23[1]};
                float sp[4];
                unsigned bits = 0;
#pragma unroll
                for (int j = 0; j < 4; j++) {
                    float vn = __fadd_rn(__fmaf_rn(ALPHA, v[i * 4 + j], d[j]), rr[j]);
                    float s = (vn >= 1.0f) ? 1.0f : 0.0f;
                    v[i * 4 + j] = (vn >= 1.0f) ? 0.0f : vn;
                    cnt[i * 4 + j] += s;
                    sp[j] = s;
                    bits |= (s != 0.f) ? (1u << j) : 0u;
                }
                *(float4*)&s_next[(size_t)(b0 + rb) * NRES + j0 + cl0] =
                    make_float4(sp[0], sp[1], sp[2], sp[3]);

                // Next-step mask: word = 32 j = 8 lanes (4 bits each).
                unsigned partial = bits << (cl0 & 31);
                unsigned grp = 0xFFu << ((lane >> 3) << 3);
                unsigned word = __reduce_or_sync(grp, partial);
                if ((lane & 7) == 0)
                    g_mask[nbuf][b0 + rb][(j0 >> 5) + (lane >> 3)] = word;
            }

            grid_barrier();
        }
        grid_barrier();   // classifier finishes step NT-1

#pragma unroll
        for (int i = 0; i < 2; i++) {
            *(float4*)&out[(size_t)NB * NCLS +
                           (size_t)(b0 + rl0 + i) * NRES + j0 + cl0] =
                make_float4(cnt[i * 4 + 0], cnt[i * 4 + 1],
                            cnt[i * 4 + 2], cnt[i * 4 + 3]);
        }
    } else {
        // ---------------- Classifier path (tid<256 active; numerics frozen) --
        const bool active = tid < 256;
        const int idx = (blk - 128) * 256 + tid;
        const int b = idx / NCLS;
        const int m = idx % NCLS;
        float vc = 0.f, cc = 0.f;

        grid_barrier();

        for (int t = 0; t <= NT; ++t) {
            if (t >= 1 && active) {
                const float* __restrict__ s_prev = g_s[t & 1];
                const float* srow = &s_prev[(size_t)b * NRES];
                const float* wrow = &Wclf[(size_t)m * NRES];
                float tot = 0.f;
#pragma unroll
                for (int blkk = 0; blkk < 4; ++blkk) {
                    float a = 0.f;
#pragma unroll 8
                    for (int n = 0; n < 256; n += 4) {
                        int base = blkk * 256 + n;
                        float4 sv = __ldcg((const float4*)(srow + base));
                        float4 wv = *(const float4*)(wrow + base);
                        a = __fmaf_rn(sv.x, wv.x, a);
                        a = __fmaf_rn(sv.y, wv.y, a);
                        a = __fmaf_rn(sv.z, wv.z, a);
                        a = __fmaf_rn(sv.w, wv.w, a);
                    }
                    tot = __fadd_rn(tot, a);
                }
                float vn = __fmaf_rn(ALPHA, vc, tot);
                float s = (vn >= 1.0f) ? 1.0f : 0.0f;
                vc = (vn >= 1.0f) ? 0.0f : vn;
                cc += s;
            }
            grid_barrier();
        }
        if (active) out[idx] = cc;
    }
}

extern "C" void kernel_launch(void* const* d_in, const int* in_sizes, int n_in,
                              void* d_out, int out_size) {
    const float* x = 0; const float* Win = 0;
    const float* Wres = 0; const float* Wclf = 0;
    for (int i = 0; i < n_in; ++i) {
        switch (in_sizes[i]) {
            case NB * NC * NT:   x    = (const float*)d_in[i]; break;
            case NRES * NC:      Win  = (const float*)d_in[i]; break;
            case NRES * NRES:    Wres = (const float*)d_in[i]; break;
            case NCLS * NRES:    Wclf = (const float*)d_in[i]; break;
        }
    }
    float* out = (float*)d_out;

    reservoir_persistent<<<NBLK, NTHR>>>(x, Win, Wres, Wclf, out);
}